// round 5
// baseline (speedup 1.0000x reference)
#include <cuda_runtime.h>

#define NF   32
#define NDOF 29
#define BLK  128          // 32 batches per block, 4 lanes per batch (one per pose row)

// ---------------------------------------------------------------------------
// Fast sincos: Cody-Waite reduction + short polys. All FMA-pipe, no MUFU.
// ---------------------------------------------------------------------------
__device__ __forceinline__ void fast_sincos(float a, float &s, float &c) {
    float q  = rintf(a * 0.63661977236758134f);   // a * 2/pi
    int   iq = (int)q;
    float r  = fmaf(q, -1.5707962513e+0f, a);
    r        = fmaf(q, -7.5497894159e-8f, r);
    float r2 = r * r;

    float ps = fmaf(r2, -1.9841270e-4f, 8.3333333e-3f);
    ps       = fmaf(r2, ps, -1.6666667e-1f);
    float sr = fmaf(r * r2, ps, r);

    float pc = fmaf(r2, -1.3888889e-3f, 4.1666668e-2f);
    pc       = fmaf(r2, pc, -5.0e-1f);
    float cr = fmaf(r2, pc, 1.0f);

    bool  sw = (iq & 1);
    float ss = sw ? cr : sr;
    float cc = sw ? sr : cr;
    unsigned sgn_s = ((unsigned)(iq & 2)) << 30;
    unsigned sgn_c = ((unsigned)((iq + 1) & 2)) << 30;
    s = __uint_as_float(__float_as_uint(ss) ^ sgn_s);
    c = __uint_as_float(__float_as_uint(cc) ^ sgn_c);
}

__global__ void __launch_bounds__(BLK, 10)
fk_kernel(const float* __restrict__ ja,        // [B, 29]
          const float* __restrict__ axes,      // [32, 3]
          const float* __restrict__ origins,   // [32, 4, 4]
          const float* __restrict__ mmult,     // [2]
          const float* __restrict__ moff,      // [2]
          const int*   __restrict__ ctrl,      // [29]
          const int*   __restrict__ msrc,      // [2]
          const int*   __restrict__ mdst,      // [2]
          const int*   __restrict__ types,     // [32]
          float*       __restrict__ out,       // [B, 32, 4, 4]
          int Bn)
{
    // Per (frame, row j in 0..2) constants, 3 x float4 each:
    //   cA = (O_j.xyz, O_j.w)
    //   cB = (O_j x k  [revolute only], O_j.k [prismatic only])
    //   cC = ((O_j.k)k - O_j.xyz [revolute only], 0)
    // L_j.xyz = cA + sn*cB + (1-cs)*cC ;  L_j.w = a*cB.w + cA.w
    __shared__ __align__(16) float4 s_cst[NF * 9];   // 4.5 KB
    __shared__ float s_ang[NF * 32];                 // final angle per (frame, batch)
    __shared__ float s_raw[32 * NDOF];
    __shared__ int   s_slot[NF];
    __shared__ int   s_mslot[NF];
    __shared__ float s_mm[NF], s_mo[NF];

    const int tid  = threadIdx.x;
    const int r    = tid & 3;        // pose row owned by this lane
    const int bt   = tid >> 2;       // batch within block (0..31)
    const int b0   = blockIdx.x * 32;
    const int gbat = b0 + bt;

    // ---- per-frame meta (ctrl slot / mimic resolution) ----
    if (tid < NF) {
        const int f = tid;
        int slot = -1;
        for (int j = 0; j < NDOF; ++j) if (ctrl[j] == f) slot = j;
        s_slot[f] = slot;
        int ms = -1; float mm = 0.f, mo = 0.f;
        for (int m = 0; m < 2; ++m) {
            if (mdst[m] == f) {
                const int sf = msrc[m];
                for (int j = 0; j < NDOF; ++j) if (ctrl[j] == sf) ms = j;
                mm = mmult[m]; mo = moff[m];
            }
        }
        s_mslot[f] = ms; s_mm[f] = mm; s_mo[f] = mo;
    }

    // ---- per (frame, row 0..2) constants: 96 pairs ----
    if (tid < NF * 3) {
        const int f  = tid / 3;
        const int rr = tid - f * 3;
        const float4 orow = *reinterpret_cast<const float4*>(origins + f * 16 + rr * 4);
        const float kx = axes[f * 3 + 0], ky = axes[f * 3 + 1], kz = axes[f * 3 + 2];
        const int   ty = types[f];
        const float vr = orow.x * kx + orow.y * ky + orow.z * kz;
        float bxx = 0.f, bxy = 0.f, bxz = 0.f;
        float cxx = 0.f, cxy = 0.f, cxz = 0.f;
        float ve  = 0.f;
        if (ty == 1) {                        // revolute
            bxx = orow.y * kz - orow.z * ky;  // O_j x k
            bxy = orow.z * kx - orow.x * kz;
            bxz = orow.x * ky - orow.y * kx;
            cxx = fmaf(vr, kx, -orow.x);      // (O_j.k)k - O_j
            cxy = fmaf(vr, ky, -orow.y);
            cxz = fmaf(vr, kz, -orow.z);
        } else if (ty == 2) {                 // prismatic
            ve = vr;
        }
        s_cst[(f * 3 + rr) * 3 + 0] = make_float4(orow.x, orow.y, orow.z, orow.w);
        s_cst[(f * 3 + rr) * 3 + 1] = make_float4(bxx, bxy, bxz, ve);
        s_cst[(f * 3 + rr) * 3 + 2] = make_float4(cxx, cxy, cxz, 0.f);
    }

    // ---- stage raw joint angles (coalesced) ----
    for (int i = tid; i < 32 * NDOF; i += BLK) {
        const int bb = i / NDOF;
        s_raw[i] = (b0 + bb < Bn) ? ja[(size_t)b0 * NDOF + i] : 0.f;
    }
    __syncthreads();

    // ---- resolve final per-(frame,batch) angles ----
    for (int i = tid; i < NF * 32; i += BLK) {
        const int f  = i >> 5;
        const int bb = i & 31;
        const int sl = s_slot[f];
        float a;
        if (sl >= 0) a = s_raw[bb * NDOF + sl];
        else {
            const int ms = s_mslot[f];
            a = (ms >= 0) ? fmaf(s_raw[bb * NDOF + ms], s_mm[f], s_mo[f]) : 0.f;
        }
        s_ang[i] = a;
    }
    __syncthreads();

    // ---- main chain: no shuffles, no syncs; every lane builds full L ----
    float p0 = (r == 0) ? 1.f : 0.f;
    float p1 = (r == 1) ? 1.f : 0.f;
    float p2 = (r == 2) ? 1.f : 0.f;
    float p3 = (r == 3) ? 1.f : 0.f;
    float q0 = 0.f, q1 = 0.f, q2 = 0.f, q3 = 0.f;   // this lane's row of pose-10

    float4* const op = reinterpret_cast<float4*>(out) + (size_t)gbat * (NF * 4) + r;
    const float*  ap = s_ang + bt;
    const bool    ok = (gbat < Bn);

    #pragma unroll 4
    for (int f = 0; f < NF; ++f) {
        if (f >= 30) { p0 = q0; p1 = q1; p2 = q2; p3 = q3; }

        const float a = ap[f * 32];
        float sn, cs;
        fast_sincos(a, sn, cs);
        const float C = 1.f - cs;

        const float4* cf = s_cst + f * 9;
        // build full local transform L (rows 0..2; row 3 = 0001 implicit)
        float L[12];
        #pragma unroll
        for (int j = 0; j < 3; ++j) {
            const float4 cA = cf[j * 3 + 0];
            const float4 cB = cf[j * 3 + 1];
            const float4 cC = cf[j * 3 + 2];
            L[j * 4 + 0] = fmaf(C, cC.x, fmaf(sn, cB.x, cA.x));
            L[j * 4 + 1] = fmaf(C, cC.y, fmaf(sn, cB.y, cA.y));
            L[j * 4 + 2] = fmaf(C, cC.z, fmaf(sn, cB.z, cA.z));
            L[j * 4 + 3] = fmaf(a, cB.w, cA.w);
        }

        // this lane's pose row update: P_r = P_r @ L
        const float n0 = fmaf(p0, L[0], fmaf(p1, L[4], p2 * L[8]));
        const float n1 = fmaf(p0, L[1], fmaf(p1, L[5], p2 * L[9]));
        const float n2 = fmaf(p0, L[2], fmaf(p1, L[6], p2 * L[10]));
        const float n3 = fmaf(p0, L[3], fmaf(p1, L[7], fmaf(p2, L[11], p3)));
        p0 = n0; p1 = n1; p2 = n2; p3 = n3;

        if (f == 10) { q0 = p0; q1 = p1; q2 = p2; q3 = p3; }

        if (ok) op[f * 4] = make_float4(p0, p1, p2, p3);
    }
}

extern "C" void kernel_launch(void* const* d_in, const int* in_sizes, int n_in,
                              void* d_out, int out_size) {
    const float* ja      = (const float*)d_in[0];
    const float* axes    = (const float*)d_in[1];
    const float* origins = (const float*)d_in[2];
    const float* mm      = (const float*)d_in[3];
    const float* mo      = (const float*)d_in[4];
    const int*   ctrl    = (const int*)d_in[5];
    const int*   msrc    = (const int*)d_in[6];
    const int*   mdst    = (const int*)d_in[7];
    const int*   types   = (const int*)d_in[8];
    float*       out     = (float*)d_out;

    const int Bn   = in_sizes[0] / NDOF;
    const int grid = (Bn + 31) / 32;          // 32 batches per block
    fk_kernel<<<grid, BLK>>>(ja, axes, origins, mm, mo, ctrl, msrc, mdst, types, out, Bn);
}

// round 6
// speedup vs baseline: 1.0891x; 1.0891x over previous
#include <cuda_runtime.h>

#define NF   32
#define NDOF 29
#define BLK  128          // 64 batches per block: 32 groups x 4 rows, each thread does 2 batches

__device__ __forceinline__ void fast_sincos(float a, float &s, float &c) {
    float q  = rintf(a * 0.63661977236758134f);
    int   iq = (int)q;
    float r  = fmaf(q, -1.5707962513e+0f, a);
    r        = fmaf(q, -7.5497894159e-8f, r);
    float r2 = r * r;
    float ps = fmaf(r2, -1.9841270e-4f, 8.3333333e-3f);
    ps       = fmaf(r2, ps, -1.6666667e-1f);
    float sr = fmaf(r * r2, ps, r);
    float pc = fmaf(r2, -1.3888889e-3f, 4.1666668e-2f);
    pc       = fmaf(r2, pc, -5.0e-1f);
    float cr = fmaf(r2, pc, 1.0f);
    bool  sw = (iq & 1);
    float ss = sw ? cr : sr;
    float cc = sw ? sr : cr;
    unsigned sgn_s = ((unsigned)(iq & 2)) << 30;
    unsigned sgn_c = ((unsigned)((iq + 1) & 2)) << 30;
    s = __uint_as_float(__float_as_uint(ss) ^ sgn_s);
    c = __uint_as_float(__float_as_uint(cc) ^ sgn_c);
}

__global__ void __launch_bounds__(BLK, 7)
fk_kernel(const float* __restrict__ ja,        // [B, 29]
          const float* __restrict__ axes,      // [32, 3]
          const float* __restrict__ origins,   // [32, 4, 4]
          const float* __restrict__ mmult,     // [2]
          const float* __restrict__ moff,      // [2]
          const int*   __restrict__ ctrl,      // [29]
          const int*   __restrict__ msrc,      // [2]
          const int*   __restrict__ mdst,      // [2]
          const int*   __restrict__ types,     // [32]
          float*       __restrict__ out,       // [B, 32, 4, 4]
          int Bn)
{
    // Per (frame, row j in 0..2) constants, 3 x float4:
    //   cA = (O_j.xyz, O_j.w)
    //   cB = (O_j x k [revolute], O_j.k [prismatic])
    //   cC = ((O_j.k)k - O_j.xyz [revolute], 0)
    // L_j.xyz = cA + sn*cB + C*cC ;  L_j.w = a*cB.w + cA.w   (C = 1-cos)
    __shared__ __align__(16) float4 s_cst[NF * 9];    // 4.5 KB
    __shared__ __align__(8)  float  s_sc[NF * 64 * 2]; // (sn, 1-cs) per (frame,batch); 16 KB
    __shared__ float s_ang[NF * 64];                  // final angle per (frame,batch); 8 KB
    __shared__ int   s_slot[NF];
    __shared__ int   s_mslot[NF];
    __shared__ float s_mm[NF], s_mo[NF];

    const int tid = threadIdx.x;
    const int r   = tid & 3;         // pose row owned by this lane
    const int g   = tid >> 2;        // batch-group within block (0..31)
    const int b0  = blockIdx.x * 64;
    const int gb0 = b0 + g;          // first batch
    const int gb1 = b0 + g + 32;     // second batch

    // ---- per-frame meta ----
    if (tid < NF) {
        const int f = tid;
        int slot = -1;
        for (int j = 0; j < NDOF; ++j) if (ctrl[j] == f) slot = j;
        s_slot[f] = slot;
        int ms = -1; float mm = 0.f, mo = 0.f;
        for (int m = 0; m < 2; ++m) {
            if (mdst[m] == f) {
                const int sf = msrc[m];
                for (int j = 0; j < NDOF; ++j) if (ctrl[j] == sf) ms = j;
                mm = mmult[m]; mo = moff[m];
            }
        }
        s_mslot[f] = ms; s_mm[f] = mm; s_mo[f] = mo;
    }

    // ---- per (frame,row) constants ----
    if (tid < NF * 3) {
        const int f  = tid / 3;
        const int rr = tid - f * 3;
        const float4 orow = *reinterpret_cast<const float4*>(origins + f * 16 + rr * 4);
        const float kx = axes[f * 3 + 0], ky = axes[f * 3 + 1], kz = axes[f * 3 + 2];
        const int   ty = types[f];
        const float vr = orow.x * kx + orow.y * ky + orow.z * kz;
        float bx = 0.f, by = 0.f, bz = 0.f, cx = 0.f, cy = 0.f, cz = 0.f, ve = 0.f;
        if (ty == 1) {
            bx = orow.y * kz - orow.z * ky;
            by = orow.z * kx - orow.x * kz;
            bz = orow.x * ky - orow.y * kx;
            cx = fmaf(vr, kx, -orow.x);
            cy = fmaf(vr, ky, -orow.y);
            cz = fmaf(vr, kz, -orow.z);
        } else if (ty == 2) {
            ve = vr;
        }
        s_cst[(f * 3 + rr) * 3 + 0] = make_float4(orow.x, orow.y, orow.z, orow.w);
        s_cst[(f * 3 + rr) * 3 + 1] = make_float4(bx, by, bz, ve);
        s_cst[(f * 3 + rr) * 3 + 2] = make_float4(cx, cy, cz, 0.f);
    }

    // ---- stage raw joint angles (aliased into s_sc; consumed before sc written) ----
    float* s_raw = s_sc;    // 64*29 = 1856 floats < 4096
    for (int i = tid; i < 64 * NDOF; i += BLK) {
        const int bb = i / NDOF;
        s_raw[i] = (b0 + bb < Bn) ? ja[(size_t)b0 * NDOF + i] : 0.f;
    }
    __syncthreads();

    // ---- resolve final angles ----
    for (int i = tid; i < NF * 64; i += BLK) {
        const int f  = i >> 6;
        const int bb = i & 63;
        const int sl = s_slot[f];
        float a;
        if (sl >= 0) a = s_raw[bb * NDOF + sl];
        else {
            const int ms = s_mslot[f];
            a = (ms >= 0) ? fmaf(s_raw[bb * NDOF + ms], s_mm[f], s_mo[f]) : 0.f;
        }
        s_ang[i] = a;
    }
    __syncthreads();       // raw fully consumed; s_sc region now reusable

    // ---- precompute (sn, 1-cs) per (frame,batch) ----
    for (int i = tid; i < NF * 64; i += BLK) {
        float sn, cs;
        fast_sincos(s_ang[i], sn, cs);
        s_sc[i * 2 + 0] = sn;
        s_sc[i * 2 + 1] = 1.f - cs;
    }
    __syncthreads();

    // ---- main chain: 2 batches per thread, shared constants, no sync ----
    float p00 = (r == 0) ? 1.f : 0.f, p01 = (r == 1) ? 1.f : 0.f;
    float p02 = (r == 2) ? 1.f : 0.f, p03 = (r == 3) ? 1.f : 0.f;
    float p10 = p00, p11 = p01, p12 = p02, p13 = p03;
    float q00 = 0.f, q01 = 0.f, q02 = 0.f, q03 = 0.f;
    float q10 = 0.f, q11 = 0.f, q12 = 0.f, q13 = 0.f;

    float4* const op0 = reinterpret_cast<float4*>(out) + (size_t)gb0 * (NF * 4) + r;
    float4* const op1 = reinterpret_cast<float4*>(out) + (size_t)gb1 * (NF * 4) + r;
    const bool ok0 = (gb0 < Bn);
    const bool ok1 = (gb1 < Bn);

    #pragma unroll 4
    for (int f = 0; f < NF; ++f) {
        if (f >= 30) {
            p00 = q00; p01 = q01; p02 = q02; p03 = q03;
            p10 = q10; p11 = q11; p12 = q12; p13 = q13;
        }

        const float2 sc0 = *reinterpret_cast<const float2*>(s_sc + (f * 64 + g)      * 2);
        const float2 sc1 = *reinterpret_cast<const float2*>(s_sc + (f * 64 + g + 32) * 2);
        const float  a0  = s_ang[f * 64 + g];
        const float  a1  = s_ang[f * 64 + g + 32];

        const float4* cf = s_cst + f * 9;
        float L0[12], L1[12];
        #pragma unroll
        for (int j = 0; j < 3; ++j) {
            const float4 cA = cf[j * 3 + 0];
            const float4 cB = cf[j * 3 + 1];
            const float4 cC = cf[j * 3 + 2];
            L0[j * 4 + 0] = fmaf(sc0.y, cC.x, fmaf(sc0.x, cB.x, cA.x));
            L0[j * 4 + 1] = fmaf(sc0.y, cC.y, fmaf(sc0.x, cB.y, cA.y));
            L0[j * 4 + 2] = fmaf(sc0.y, cC.z, fmaf(sc0.x, cB.z, cA.z));
            L0[j * 4 + 3] = fmaf(a0, cB.w, cA.w);
            L1[j * 4 + 0] = fmaf(sc1.y, cC.x, fmaf(sc1.x, cB.x, cA.x));
            L1[j * 4 + 1] = fmaf(sc1.y, cC.y, fmaf(sc1.x, cB.y, cA.y));
            L1[j * 4 + 2] = fmaf(sc1.y, cC.z, fmaf(sc1.x, cB.z, cA.z));
            L1[j * 4 + 3] = fmaf(a1, cB.w, cA.w);
        }

        // P_r = P_r @ L  (row 3 of L = 0001 implicit)
        {
            const float n0 = fmaf(p00, L0[0], fmaf(p01, L0[4], p02 * L0[8]));
            const float n1 = fmaf(p00, L0[1], fmaf(p01, L0[5], p02 * L0[9]));
            const float n2 = fmaf(p00, L0[2], fmaf(p01, L0[6], p02 * L0[10]));
            const float n3 = fmaf(p00, L0[3], fmaf(p01, L0[7], fmaf(p02, L0[11], p03)));
            p00 = n0; p01 = n1; p02 = n2; p03 = n3;
        }
        {
            const float n0 = fmaf(p10, L1[0], fmaf(p11, L1[4], p12 * L1[8]));
            const float n1 = fmaf(p10, L1[1], fmaf(p11, L1[5], p12 * L1[9]));
            const float n2 = fmaf(p10, L1[2], fmaf(p11, L1[6], p12 * L1[10]));
            const float n3 = fmaf(p10, L1[3], fmaf(p11, L1[7], fmaf(p12, L1[11], p13)));
            p10 = n0; p11 = n1; p12 = n2; p13 = n3;
        }

        if (f == 10) {
            q00 = p00; q01 = p01; q02 = p02; q03 = p03;
            q10 = p10; q11 = p11; q12 = p12; q13 = p13;
        }

        if (ok0) op0[f * 4] = make_float4(p00, p01, p02, p03);
        if (ok1) op1[f * 4] = make_float4(p10, p11, p12, p13);
    }
}

extern "C" void kernel_launch(void* const* d_in, const int* in_sizes, int n_in,
                              void* d_out, int out_size) {
    const float* ja      = (const float*)d_in[0];
    const float* axes    = (const float*)d_in[1];
    const float* origins = (const float*)d_in[2];
    const float* mm      = (const float*)d_in[3];
    const float* mo      = (const float*)d_in[4];
    const int*   ctrl    = (const int*)d_in[5];
    const int*   msrc    = (const int*)d_in[6];
    const int*   mdst    = (const int*)d_in[7];
    const int*   types   = (const int*)d_in[8];
    float*       out     = (float*)d_out;

    const int Bn   = in_sizes[0] / NDOF;
    const int grid = (Bn + 63) / 64;          // 64 batches per block
    fk_kernel<<<grid, BLK>>>(ja, axes, origins, mm, mo, ctrl, msrc, mdst, types, out, Bn);
}

// round 7
// speedup vs baseline: 1.2290x; 1.1285x over previous
#include <cuda_runtime.h>

#define NF   32
#define NDOF 29
#define BLK  128            // 128 batches per block, 1 thread per batch
#define SSTR 52             // slab floats per batch (13 float4, bank-staggered)

__device__ __forceinline__ void fast_sincos(float a, float &s, float &c) {
    float q  = rintf(a * 0.63661977236758134f);
    int   iq = (int)q;
    float r  = fmaf(q, -1.5707962513e+0f, a);
    r        = fmaf(q, -7.5497894159e-8f, r);
    float r2 = r * r;
    float ps = fmaf(r2, -1.9841270e-4f, 8.3333333e-3f);
    ps       = fmaf(r2, ps, -1.6666667e-1f);
    float sr = fmaf(r * r2, ps, r);
    float pc = fmaf(r2, -1.3888889e-3f, 4.1666668e-2f);
    pc       = fmaf(r2, pc, -5.0e-1f);
    float cr = fmaf(r2, pc, 1.0f);
    bool  sw = (iq & 1);
    float ss = sw ? cr : sr;
    float cc = sw ? sr : cr;
    unsigned sgn_s = ((unsigned)(iq & 2)) << 30;
    unsigned sgn_c = ((unsigned)((iq + 1) & 2)) << 30;
    s = __uint_as_float(__float_as_uint(ss) ^ sgn_s);
    c = __uint_as_float(__float_as_uint(cc) ^ sgn_c);
}

__global__ void __launch_bounds__(BLK, 4)
fk_kernel(const float* __restrict__ ja,        // [B, 29]
          const float* __restrict__ axes,      // [32, 3]
          const float* __restrict__ origins,   // [32, 4, 4]
          const float* __restrict__ mmult,     // [2]
          const float* __restrict__ moff,      // [2]
          const int*   __restrict__ ctrl,      // [29]
          const int*   __restrict__ msrc,      // [2]
          const int*   __restrict__ mdst,      // [2]
          const int*   __restrict__ types,     // [32]
          float*       __restrict__ out,       // [B, 32, 4, 4]
          int Bn)
{
    // Per (frame, row j in 0..2) constants, 3 x float4:
    //   cA = (O_j.xyz, O_j.w)
    //   cB = (O_j x k [revolute], O_j.k [prismatic])
    //   cC = ((O_j.k)k - O_j.xyz [revolute], 0)
    // L_j.xyz = cA + sn*cB + C*cC ;  L_j.w = a*cB.w + cA.w  (C = 1-cos)
    __shared__ __align__(16) float4 s_cst[NF * 9];              // 4.5 KB
    __shared__ __align__(16) float  s_slab[4 * 32 * SSTR];      // 26 KB (warp-private quarters)
    __shared__ float s_angF[NF * BLK];                          // 16 KB
    __shared__ int   s_slot[NF];
    __shared__ int   s_mslot[NF];
    __shared__ float s_mm[NF], s_mo[NF];

    const int tid  = threadIdx.x;
    const int lane = tid & 31;
    const int wid  = tid >> 5;
    const int b0   = blockIdx.x * BLK;

    // ---- per-frame meta ----
    if (tid < NF) {
        const int f = tid;
        int slot = -1;
        for (int j = 0; j < NDOF; ++j) if (ctrl[j] == f) slot = j;
        s_slot[f] = slot;
        int ms = -1; float mm = 0.f, mo = 0.f;
        for (int m = 0; m < 2; ++m) {
            if (mdst[m] == f) {
                const int sf = msrc[m];
                for (int j = 0; j < NDOF; ++j) if (ctrl[j] == sf) ms = j;
                mm = mmult[m]; mo = moff[m];
            }
        }
        s_mslot[f] = ms; s_mm[f] = mm; s_mo[f] = mo;
    }

    // ---- per (frame,row) constants ----
    if (tid < NF * 3) {
        const int f  = tid / 3;
        const int rr = tid - f * 3;
        const float4 orow = *reinterpret_cast<const float4*>(origins + f * 16 + rr * 4);
        const float kx = axes[f * 3 + 0], ky = axes[f * 3 + 1], kz = axes[f * 3 + 2];
        const int   ty = types[f];
        const float vr = orow.x * kx + orow.y * ky + orow.z * kz;
        float bx = 0.f, by = 0.f, bz = 0.f, cx = 0.f, cy = 0.f, cz = 0.f, ve = 0.f;
        if (ty == 1) {
            bx = orow.y * kz - orow.z * ky;
            by = orow.z * kx - orow.x * kz;
            bz = orow.x * ky - orow.y * kx;
            cx = fmaf(vr, kx, -orow.x);
            cy = fmaf(vr, ky, -orow.y);
            cz = fmaf(vr, kz, -orow.z);
        } else if (ty == 2) {
            ve = vr;
        }
        s_cst[(f * 3 + rr) * 3 + 0] = make_float4(orow.x, orow.y, orow.z, orow.w);
        s_cst[(f * 3 + rr) * 3 + 1] = make_float4(bx, by, bz, ve);
        s_cst[(f * 3 + rr) * 3 + 2] = make_float4(cx, cy, cz, 0.f);
    }

    // ---- stage raw joint angles into slab region (aliased), coalesced ----
    float* s_raw = s_slab;                 // 128*29 = 3712 floats <= 6656 ✓
    for (int i = tid; i < BLK * NDOF; i += BLK) {
        const int bb = i / NDOF;
        s_raw[i] = (b0 + bb < Bn) ? ja[(size_t)b0 * NDOF + i] : 0.f;
    }
    __syncthreads();

    // ---- resolve final per-(frame,batch) angles ----
    for (int i = tid; i < NF * BLK; i += BLK) {
        const int f  = i >> 7;
        const int bb = i & 127;
        const int sl = s_slot[f];
        float a;
        if (sl >= 0) a = s_raw[bb * NDOF + sl];
        else {
            const int ms = s_mslot[f];
            a = (ms >= 0) ? fmaf(s_raw[bb * NDOF + ms], s_mm[f], s_mo[f]) : 0.f;
        }
        s_angF[i] = a;
    }
    __syncthreads();        // raw fully consumed; slab reusable

    // ---- main chain: warp-autonomous, staged coalesced flush ----
    float P[12];
    #pragma unroll
    for (int j = 0; j < 12; ++j) P[j] = 0.f;
    P[0] = 1.f; P[5] = 1.f; P[10] = 1.f;
    float Q[12];
    #pragma unroll
    for (int j = 0; j < 12; ++j) Q[j] = 0.f;

    float* const wslab = s_slab + wid * (32 * SSTR);
    float4* const out4 = reinterpret_cast<float4*>(out);

    #pragma unroll
    for (int c = 0; c < NF / 4; ++c) {
        #pragma unroll
        for (int ff = 0; ff < 4; ++ff) {
            const int f = c * 4 + ff;
            if (f >= 30) {
                #pragma unroll
                for (int j = 0; j < 12; ++j) P[j] = Q[j];
            }
            const float a = s_angF[f * BLK + tid];
            float sn, cs;
            fast_sincos(a, sn, cs);
            const float C = 1.f - cs;

            const float4* cf = s_cst + f * 9;
            float L[12];
            #pragma unroll
            for (int j = 0; j < 3; ++j) {
                const float4 cA = cf[j * 3 + 0];
                const float4 cB = cf[j * 3 + 1];
                const float4 cC = cf[j * 3 + 2];
                L[j * 4 + 0] = fmaf(C, cC.x, fmaf(sn, cB.x, cA.x));
                L[j * 4 + 1] = fmaf(C, cC.y, fmaf(sn, cB.y, cA.y));
                L[j * 4 + 2] = fmaf(C, cC.z, fmaf(sn, cB.z, cA.z));
                L[j * 4 + 3] = fmaf(a, cB.w, cA.w);
            }

            // P = P @ L (rows of P independent; L row3 = 0001)
            #pragma unroll
            for (int rr = 0; rr < 3; ++rr) {
                const float p0 = P[rr * 4 + 0], p1 = P[rr * 4 + 1];
                const float p2 = P[rr * 4 + 2], p3 = P[rr * 4 + 3];
                P[rr * 4 + 0] = fmaf(p0, L[0], fmaf(p1, L[4], p2 * L[8]));
                P[rr * 4 + 1] = fmaf(p0, L[1], fmaf(p1, L[5], p2 * L[9]));
                P[rr * 4 + 2] = fmaf(p0, L[2], fmaf(p1, L[6], p2 * L[10]));
                P[rr * 4 + 3] = fmaf(p0, L[3], fmaf(p1, L[7], fmaf(p2, L[11], p3)));
            }
            if (f == 10) {
                #pragma unroll
                for (int j = 0; j < 12; ++j) Q[j] = P[j];
            }

            // stage this frame's 3 rows into warp-private slab
            float4* sp = reinterpret_cast<float4*>(wslab + lane * SSTR + ff * 12);
            sp[0] = make_float4(P[0], P[1], P[2],  P[3]);
            sp[1] = make_float4(P[4], P[5], P[6],  P[7]);
            sp[2] = make_float4(P[8], P[9], P[10], P[11]);
        }

        __syncwarp();

        // flush: 2 batches x 256 B contiguous per iteration (fully coalesced)
        #pragma unroll
        for (int it = 0; it < 16; ++it) {
            const int b = it * 2 + (lane >> 4);    // warp-local batch
            const int w = lane & 15;               // f*4+r within chunk
            const int fi = w >> 2;
            const int rr = w & 3;
            float4 val;
            if (rr < 3) val = *reinterpret_cast<const float4*>(wslab + b * SSTR + fi * 12 + rr * 4);
            else        val = make_float4(0.f, 0.f, 0.f, 1.f);
            const int gbat = b0 + (wid << 5) + b;
            if (gbat < Bn)
                out4[(size_t)gbat * (NF * 4) + c * 16 + w] = val;
        }

        __syncwarp();
    }
}

extern "C" void kernel_launch(void* const* d_in, const int* in_sizes, int n_in,
                              void* d_out, int out_size) {
    const float* ja      = (const float*)d_in[0];
    const float* axes    = (const float*)d_in[1];
    const float* origins = (const float*)d_in[2];
    const float* mm      = (const float*)d_in[3];
    const float* mo      = (const float*)d_in[4];
    const int*   ctrl    = (const int*)d_in[5];
    const int*   msrc    = (const int*)d_in[6];
    const int*   mdst    = (const int*)d_in[7];
    const int*   types   = (const int*)d_in[8];
    float*       out     = (float*)d_out;

    const int Bn   = in_sizes[0] / NDOF;
    const int grid = (Bn + BLK - 1) / BLK;
    fk_kernel<<<grid, BLK>>>(ja, axes, origins, mm, mo, ctrl, msrc, mdst, types, out, Bn);
}